// round 12
// baseline (speedup 1.0000x reference)
#include <cuda_runtime.h>
#include <cuda_fp16.h>

// GAT 3-layer forward on GB300.
// CSR-by-dst build (packed (src,dst) slots), per layer: dense GEMM with fused
// score epilogue (fp16 features + fp32 scores), edge-parallel weight
// precompute packing (src, w) into one 8B word, warp-per-node aggregation
// with half-warp-per-edge uint4 gathers. Layer-3 128->5 GEMM is fused into
// the layer-2 aggregation epilogue (no intermediate 25.6MB tensor).

#define NN   50000
#define EE   1600000
#define ET   (NN + EE)     // edges + self loops
#define HID  128
#define IND  13
#define OUTD 5
#define NB   196           // ceil(NN/256)

// ---------------- scratch (device globals; no allocation allowed) ----------
__device__ __align__(16) __half g_h16[NN * HID];  // fp16 features for gathers
__device__ __align__(16) float g_hB[NN * HID];    // fp32 agg outputs / GEMM inputs
__device__ __align__(16) float g_h3[NN * OUTD];
__device__ float g_as[NN];
__device__ float g_ad[NN];
__device__ int   g_deg[NN];
__device__ int   g_roff[NN + 1];
__device__ int   g_cur[NN];
__device__ __align__(16) long long g_csrp[ET];    // packed: low=src, high=dst
__device__ __align__(16) long long g_swp[ET];     // packed: low=src, high=f32 weight
__device__ int   g_srcv[EE];
__device__ int   g_dstv[EE];
__device__ int   g_bsum[256];
__device__ int   g_boff[256];
__device__ int   g_is64;

#define FMA_F32X2(d, a, b, c) \
    asm("fma.rn.f32x2 %0, %1, %2, %3;" : "=l"(d) : "l"(a), "l"(b), "l"(c))

__device__ __forceinline__ unsigned long long pack_f32x2(float lo, float hi) {
    unsigned long long r;
    unsigned ulo = __float_as_uint(lo), uhi = __float_as_uint(hi);
    asm("mov.b64 %0, {%1, %2};" : "=l"(r) : "r"(ulo), "r"(uhi));
    return r;
}
__device__ __forceinline__ void unpack_f32x2(unsigned long long v, float& lo, float& hi) {
    unsigned ulo, uhi;
    asm("mov.b64 {%0, %1}, %2;" : "=r"(ulo), "=r"(uhi) : "l"(v));
    lo = __uint_as_float(ulo);
    hi = __uint_as_float(uhi);
}

__device__ __forceinline__ float warp_sum(float v) {
#pragma unroll
    for (int o = 16; o > 0; o >>= 1) v += __shfl_xor_sync(0xffffffffu, v, o);
    return v;
}
__device__ __forceinline__ float lrelu(float v) { return v > 0.f ? v : 0.2f * v; }

// ---------------- detect edge dtype + init degrees (fused) ------------------
__global__ void init_kernel(const unsigned* __restrict__ w, int n) {
    int i = blockIdx.x * blockDim.x + threadIdx.x;
    if (i < n) g_deg[i] = 1;  // self loop
    if (blockIdx.x == 0 && threadIdx.x == 0) {
        int all0 = 1;
        for (int k = 1; k < 64; k += 2) all0 &= (w[k] == 0u);
        g_is64 = all0;
    }
}

__global__ void convert_count_kernel(const void* __restrict__ ei, int E) {
    int i = blockIdx.x * blockDim.x + threadIdx.x;
    if (i >= E) return;
    int s, d;
    if (g_is64) {
        const long long* p = (const long long*)ei;
        s = (int)p[i];
        d = (int)p[E + i];
    } else {
        const int* p = (const int*)ei;
        s = p[i];
        d = p[E + i];
    }
    g_srcv[i] = s;
    g_dstv[i] = d;
    atomicAdd(&g_deg[d], 1);
}

// ---------------- two-level parallel exclusive scan of g_deg ----------------
__global__ void scan1_kernel() {
    int i = blockIdx.x * 256 + threadIdx.x;
    int v = (i < NN) ? g_deg[i] : 0;
#pragma unroll
    for (int o = 16; o > 0; o >>= 1) v += __shfl_xor_sync(0xffffffffu, v, o);
    __shared__ int sw[8];
    if ((threadIdx.x & 31) == 0) sw[threadIdx.x >> 5] = v;
    __syncthreads();
    if (threadIdx.x == 0) {
        int t = 0;
#pragma unroll
        for (int k = 0; k < 8; k++) t += sw[k];
        g_bsum[blockIdx.x] = t;
    }
}

// single warp, shuffle-based exclusive scan of the 196 block sums
__global__ void scan2_kernel(int E) {
    const int C = (NB + 31) / 32;  // 7 per lane
    int lane = threadIdx.x;
    int beg = lane * C;
    int vals[C];
    int s = 0;
#pragma unroll
    for (int j = 0; j < C; j++) {
        int idx = beg + j;
        int v = (idx < NB) ? g_bsum[idx] : 0;
        vals[j] = s;          // exclusive within lane
        s += v;
    }
    int t = s;
#pragma unroll
    for (int o = 1; o < 32; o <<= 1) {
        int u = __shfl_up_sync(0xffffffffu, t, o);
        if (lane >= o) t += u;
    }
    int ex = t - s;           // exclusive across lanes
#pragma unroll
    for (int j = 0; j < C; j++) {
        int idx = beg + j;
        if (idx < NB) g_boff[idx] = ex + vals[j];
    }
    if (lane == 0) g_roff[NN] = NN + E;
}

__global__ void scan3_kernel() {
    __shared__ int sh[256];
    int tid = threadIdx.x;
    int i = blockIdx.x * 256 + tid;
    int v = (i < NN) ? g_deg[i] : 0;
    sh[tid] = v;
    __syncthreads();
    for (int off = 1; off < 256; off <<= 1) {
        int t = (tid >= off) ? sh[tid - off] : 0;
        __syncthreads();
        sh[tid] += t;
        __syncthreads();
    }
    if (i < NN) {
        int o = g_boff[blockIdx.x] + sh[tid] - v;
        g_roff[i] = o;
        g_cur[i]  = o;
    }
}

__global__ void scatter_kernel(int E, int n) {
    int i = blockIdx.x * blockDim.x + threadIdx.x;
    int total = n + E;
    if (i >= total) return;
    int src, dst;
    if (i < n) { src = i; dst = i; }
    else       { int e = i - n; src = g_srcv[e]; dst = g_dstv[e]; }
    int p = atomicAdd(&g_cur[dst], 1);
    g_csrp[p] = (long long)(unsigned)src | ((long long)dst << 32);
}

// ---------------- per-edge softmax weights (streaming, per layer) -----------
// reads (src,dst), writes (src, w) — agg kernels then load ONE 8B word/edge.
__global__ void weights_kernel(int total) {
    int i = blockIdx.x * blockDim.x + threadIdx.x;
    if (i >= total) return;
    long long v = g_csrp[i];
    int s = (int)v;
    int d = (int)(v >> 32);
    float w = __expf(fminf(lrelu(g_as[s] + g_ad[d]), 80.f));
    g_swp[i] = (long long)(unsigned)s | ((long long)__float_as_uint(w) << 32);
}

// ---------------- GEMMs with fused score epilogue ---------------------------
// Layer 1: [N,13] @ [13,128] -> g_h16 (+ scores g_as/g_ad)
__global__ void gemm13_kernel(const float* __restrict__ x, const float* __restrict__ W,
                              const float* __restrict__ a_s, const float* __restrict__ a_d) {
    __shared__ float Ws[IND * HID];
    __shared__ float xs[16 * IND];
    __shared__ __align__(16) float hs[16 * HID];
    int tid = threadIdx.x;
    for (int j = tid; j < IND * HID; j += 128) Ws[j] = W[j];
    int base = blockIdx.x * 16;
    for (int j = tid; j < 16 * IND; j += 128) {
        int r = j / IND, k = j % IND;
        xs[j] = x[(base + r) * IND + k];
    }
    __syncthreads();
#pragma unroll 4
    for (int r = 0; r < 16; r++) {
        float acc = 0.f;
#pragma unroll
        for (int k = 0; k < IND; k++) acc += xs[r * IND + k] * Ws[k * HID + tid];
        g_h16[(base + r) * HID + tid] = __float2half(acc);
        hs[r * HID + tid] = acc;
    }
    __syncthreads();
    int wid = tid >> 5, lane = tid & 31;
    float4 s4 = ((const float4*)a_s)[lane];
    float4 d4 = ((const float4*)a_d)[lane];
#pragma unroll
    for (int i = 0; i < 4; i++) {
        int r = wid * 4 + i;
        float4 hv = ((const float4*)(hs + r * HID))[lane];
        float ps = hv.x * s4.x + hv.y * s4.y + hv.z * s4.z + hv.w * s4.w;
        float pd = hv.x * d4.x + hv.y * d4.y + hv.z * d4.z + hv.w * d4.w;
        ps = warp_sum(ps);
        pd = warp_sum(pd);
        if (lane == 0) { g_as[base + r] = ps; g_ad[base + r] = pd; }
    }
}

// Layer 2: g_hB [N,128] @ W2 [128,128] -> g_h16 (+ scores).
#define GROWS 32
__global__ void __launch_bounds__(128) gemm128_kernel(const float* __restrict__ W,
                                                      const float* __restrict__ a_s,
                                                      const float* __restrict__ a_d) {
    __shared__ __align__(16) float hs[GROWS * HID];  // 16KB, reused for epilogue
    int tid = threadIdx.x;
    int base = blockIdx.x * GROWS;
    const float4* hin4 = (const float4*)g_hB;
    float4* hs4 = (float4*)hs;
    for (int j = tid; j < GROWS * 32; j += 128) {
        int r = j >> 5, q = j & 31;
        int row = base + r;
        hs4[j] = (row < NN) ? hin4[row * 32 + q] : make_float4(0.f, 0.f, 0.f, 0.f);
    }
    __syncthreads();

    unsigned long long acc[GROWS];
#pragma unroll
    for (int r = 0; r < GROWS; r++) acc[r] = 0ull;

    for (int kq = 0; kq < 32; kq++) {
        int k0 = 4 * kq;
        float w0 = __ldg(&W[(k0 + 0) * HID + tid]);
        float w1 = __ldg(&W[(k0 + 1) * HID + tid]);
        float w2 = __ldg(&W[(k0 + 2) * HID + tid]);
        float w3 = __ldg(&W[(k0 + 3) * HID + tid]);
        unsigned long long b01 = pack_f32x2(w0, w1);
        unsigned long long b23 = pack_f32x2(w2, w3);
#pragma unroll
        for (int r = 0; r < GROWS; r++) {
            const ulonglong2 a = *(const ulonglong2*)&hs[r * HID + k0];
            FMA_F32X2(acc[r], a.x, b01, acc[r]);
            FMA_F32X2(acc[r], a.y, b23, acc[r]);
        }
    }
    __syncthreads();
#pragma unroll
    for (int r = 0; r < GROWS; r++) {
        float lo, hi;
        unpack_f32x2(acc[r], lo, hi);
        float v = lo + hi;
        hs[r * HID + tid] = v;
        if (base + r < NN) g_h16[(base + r) * HID + tid] = __float2half(v);
    }
    __syncthreads();
    int wid = tid >> 5, lane = tid & 31;
    float4 s4 = ((const float4*)a_s)[lane];
    float4 d4 = ((const float4*)a_d)[lane];
#pragma unroll
    for (int i = 0; i < 8; i++) {
        int r = wid * 8 + i;
        float4 hv = ((const float4*)(hs + r * HID))[lane];
        float ps = hv.x * s4.x + hv.y * s4.y + hv.z * s4.z + hv.w * s4.w;
        float pd = hv.x * d4.x + hv.y * d4.y + hv.z * d4.z + hv.w * d4.w;
        ps = warp_sum(ps);
        pd = warp_sum(pd);
        if (lane == 0 && base + r < NN) { g_as[base + r] = ps; g_ad[base + r] = pd; }
    }
}

// ---------------- 128-dim aggregation core (half-warp per edge) -------------
// Computes the node's normalized+biased+relu'd 128-dim output into acc[8] of
// lanes 0..15 (covering columns l16*8..l16*8+7). Returns true if lane<16.
__device__ __forceinline__ bool agg128_core(int warp, int lane,
                                            const float* __restrict__ bias,
                                            float (&acc)[8], int& l16out) {
    int e0 = g_roff[warp], e1 = g_roff[warp + 1];
    int half = lane >> 4;
    int l16  = lane & 15;
    l16out = l16;

#pragma unroll
    for (int j = 0; j < 8; j++) acc[j] = 0.f;
    float s = 0.f;

    int e = e0;
    for (; e + 7 < e1; e += 8) {
#pragma unroll
        for (int p = 0; p < 4; p++) {
            int idx = e + 2 * p + half;
            long long sw = g_swp[idx];
            int src = (int)sw;
            float w = __uint_as_float((unsigned)(sw >> 32));
            const uint4 u = ((const uint4*)(g_h16 + src * HID))[l16];
            s += w;
            float2 f0 = __half22float2(*(const __half2*)&u.x);
            float2 f1 = __half22float2(*(const __half2*)&u.y);
            float2 f2 = __half22float2(*(const __half2*)&u.z);
            float2 f3 = __half22float2(*(const __half2*)&u.w);
            acc[0] += w * f0.x; acc[1] += w * f0.y;
            acc[2] += w * f1.x; acc[3] += w * f1.y;
            acc[4] += w * f2.x; acc[5] += w * f2.y;
            acc[6] += w * f3.x; acc[7] += w * f3.y;
        }
    }
    for (; e < e1; e++) {
        long long sw = g_swp[e];
        int src = (int)sw;
        float w = (half == 0) ? __uint_as_float((unsigned)(sw >> 32)) : 0.f;
        const uint4 u = ((const uint4*)(g_h16 + src * HID))[l16];
        s += w;
        float2 f0 = __half22float2(*(const __half2*)&u.x);
        float2 f1 = __half22float2(*(const __half2*)&u.y);
        float2 f2 = __half22float2(*(const __half2*)&u.z);
        float2 f3 = __half22float2(*(const __half2*)&u.w);
        acc[0] += w * f0.x; acc[1] += w * f0.y;
        acc[2] += w * f1.x; acc[3] += w * f1.y;
        acc[4] += w * f2.x; acc[5] += w * f2.y;
        acc[6] += w * f3.x; acc[7] += w * f3.y;
    }

    s += __shfl_down_sync(0xffffffffu, s, 16);
#pragma unroll
    for (int j = 0; j < 8; j++) acc[j] += __shfl_down_sync(0xffffffffu, acc[j], 16);

    float inv = 1.f / s;
    const float4* b4 = (const float4*)(bias + l16 * 8);
    float4 bA = b4[0], bB = b4[1];
    acc[0] = fmaxf(acc[0] * inv + bA.x, 0.f);
    acc[1] = fmaxf(acc[1] * inv + bA.y, 0.f);
    acc[2] = fmaxf(acc[2] * inv + bA.z, 0.f);
    acc[3] = fmaxf(acc[3] * inv + bA.w, 0.f);
    acc[4] = fmaxf(acc[4] * inv + bB.x, 0.f);
    acc[5] = fmaxf(acc[5] * inv + bB.y, 0.f);
    acc[6] = fmaxf(acc[6] * inv + bB.z, 0.f);
    acc[7] = fmaxf(acc[7] * inv + bB.w, 0.f);
    return lane < 16;
}

// Layer-1 aggregation: write fp32 output to g_hB (feeds gemm128)
__global__ void agg128_kernel(const float* __restrict__ bias) {
    int warp = (blockIdx.x * blockDim.x + threadIdx.x) >> 5;
    int lane = threadIdx.x & 31;
    if (warp >= NN) return;
    float acc[8];
    int l16;
    if (agg128_core(warp, lane, bias, acc, l16)) {
        float4* dst = (float4*)(g_hB + warp * HID + l16 * 8);
        dst[0] = make_float4(acc[0], acc[1], acc[2], acc[3]);
        dst[1] = make_float4(acc[4], acc[5], acc[6], acc[7]);
    }
}

// Layer-2 aggregation with fused layer-3 GEMM (128->5) + scores.
// The 128-dim activation never touches global memory.
__global__ void agg128_l3_kernel(const float* __restrict__ bias,
                                 const float* __restrict__ W3,
                                 const float* __restrict__ a_s,
                                 const float* __restrict__ a_d) {
    __shared__ float Ws[HID * OUTD];
    int tid = threadIdx.x;
    for (int j = tid; j < HID * OUTD; j += blockDim.x) Ws[j] = W3[j];
    __syncthreads();

    int warp = (blockIdx.x * blockDim.x + tid) >> 5;
    int lane = tid & 31;
    if (warp >= NN) return;
    float acc[8];
    int l16;
    agg128_core(warp, lane, bias, acc, l16);

    // 128->5 GEMM within warp: lane l16 holds features k=l16*8..l16*8+7
    float o[OUTD];
#pragma unroll
    for (int c = 0; c < OUTD; c++) {
        float p = 0.f;
#pragma unroll
        for (int j = 0; j < 8; j++) p += acc[j] * Ws[(l16 * 8 + j) * OUTD + c];
#pragma unroll
        for (int off = 8; off > 0; off >>= 1)
            p += __shfl_down_sync(0xffffffffu, p, off);
        o[c] = p;  // valid on lane 0
    }
    if (lane == 0) {
        float as = 0.f, ad = 0.f;
#pragma unroll
        for (int c = 0; c < OUTD; c++) {
            g_h3[warp * OUTD + c] = o[c];
            as += o[c] * a_s[c];
            ad += o[c] * a_d[c];
        }
        g_as[warp] = as;
        g_ad[warp] = ad;
    }
}

// ---------------- 5-dim aggregation + log_softmax -> d_out ------------------
__global__ void agg5_kernel(const float* __restrict__ b3, float* __restrict__ out) {
    int warp = (blockIdx.x * blockDim.x + threadIdx.x) >> 5;
    int lane = threadIdx.x & 31;
    if (warp >= NN) return;
    int e = g_roff[warp], end = g_roff[warp + 1];

    float s = 0.f, acc = 0.f;
    for (; e + 1 < end; e += 2) {
        long long sw0 = g_swp[e], sw1 = g_swp[e + 1];
        int s0 = (int)sw0, s1 = (int)sw1;
        float w0 = __uint_as_float((unsigned)(sw0 >> 32));
        float w1 = __uint_as_float((unsigned)(sw1 >> 32));
        s += w0 + w1;
        if (lane < OUTD) acc += w0 * g_h3[s0 * OUTD + lane] + w1 * g_h3[s1 * OUTD + lane];
    }
    if (e < end) {
        long long sw0 = g_swp[e];
        int s0 = (int)sw0;
        float w0 = __uint_as_float((unsigned)(sw0 >> 32));
        s += w0;
        if (lane < OUTD) acc += w0 * g_h3[s0 * OUTD + lane];
    }

    float v = (lane < OUTD) ? (acc / s + b3[lane]) : -1e30f;
    float m5 = v;
#pragma unroll
    for (int o = 4; o > 0; o >>= 1) m5 = fmaxf(m5, __shfl_xor_sync(0xffffffffu, m5, o));
    float ex = (lane < OUTD) ? __expf(v - m5) : 0.f;
#pragma unroll
    for (int o = 4; o > 0; o >>= 1) ex += __shfl_xor_sync(0xffffffffu, ex, o);
    if (lane < OUTD) out[warp * OUTD + lane] = v - m5 - logf(ex);
}

// ---------------- launch ----------------------------------------------------
extern "C" void kernel_launch(void* const* d_in, const int* in_sizes, int n_in,
                              void* d_out, int out_size) {
    const float* x      = (const float*)d_in[0];
    const void*  ei     = d_in[1];
    const float* W1     = (const float*)d_in[2];
    const float* a_src1 = (const float*)d_in[3];
    const float* a_dst1 = (const float*)d_in[4];
    const float* b1     = (const float*)d_in[5];
    const float* W2     = (const float*)d_in[6];
    const float* a_src2 = (const float*)d_in[7];
    const float* a_dst2 = (const float*)d_in[8];
    const float* b2     = (const float*)d_in[9];
    const float* W3     = (const float*)d_in[10];
    const float* a_src3 = (const float*)d_in[11];
    const float* a_dst3 = (const float*)d_in[12];
    const float* b3     = (const float*)d_in[13];
    float* out = (float*)d_out;

    const int E = in_sizes[1] / 2;
    const int N = NN;
    const int total = N + E;

    // CSR build
    init_kernel<<<NB, 256>>>((const unsigned*)ei, N);
    convert_count_kernel<<<(E + 255) / 256, 256>>>(ei, E);
    scan1_kernel<<<NB, 256>>>();
    scan2_kernel<<<1, 32>>>(E);
    scan3_kernel<<<NB, 256>>>();
    scatter_kernel<<<(total + 255) / 256, 256>>>(E, N);

    // Layer 1
    gemm13_kernel<<<N / 16, 128>>>(x, W1, a_src1, a_dst1);
    weights_kernel<<<(total + 255) / 256, 256>>>(total);
    agg128_kernel<<<N / 8, 256>>>(b1);

    // Layer 2 (+ fused layer-3 transform)
    gemm128_kernel<<<(N + GROWS - 1) / GROWS, 128>>>(W2, a_src2, a_dst2);
    weights_kernel<<<(total + 255) / 256, 256>>>(total);
    agg128_l3_kernel<<<N / 8, 256>>>(b2, W3, a_src3, a_dst3);

    // Layer 3 aggregation + log_softmax
    weights_kernel<<<(total + 255) / 256, 256>>>(total);
    agg5_kernel<<<N / 8, 256>>>(b3, out);
}

// round 13
// speedup vs baseline: 1.0144x; 1.0144x over previous
#include <cuda_runtime.h>
#include <cuda_fp16.h>

// GAT 3-layer forward on GB300. R10 structure (best known) + tail fixes:
// CSR-by-dst build (merged scan), per layer: dense GEMM with fused score
// epilogue (fp16 features + fp32 scores), edge-parallel weight precompute
// (layers 1-2), warp-per-node aggregation with half-warp-per-edge uint4
// gathers; agg5 computes weights inline (dst-uniform ad), padded g_h3 rows.

#define NN   50000
#define EE   1600000
#define ET   (NN + EE)     // edges + self loops
#define HID  128
#define IND  13
#define OUTD 5
#define H3S  8             // padded row stride for g_h3 (32B sectors)
#define NB   196           // ceil(NN/256)

// ---------------- scratch (device globals; no allocation allowed) ----------
__device__ __align__(16) __half g_h16[NN * HID];  // fp16 features for gathers
__device__ __align__(16) float g_hB[NN * HID];    // fp32 agg outputs / GEMM inputs
__device__ __align__(16) float g_h3[NN * H3S];    // layer-3 features, padded rows
__device__ float g_as[NN];
__device__ float g_ad[NN];
__device__ int   g_deg[NN];
__device__ int   g_roff[NN + 1];
__device__ int   g_cur[NN];
__device__ __align__(16) long long g_csrp[ET];    // packed: low=src, high=dst
__device__ __align__(16) float g_w[ET];           // per-edge softmax weight
__device__ int   g_srcv[EE];
__device__ int   g_dstv[EE];
__device__ int   g_bsum[256];
__device__ int   g_is64;

#define FMA_F32X2(d, a, b, c) \
    asm("fma.rn.f32x2 %0, %1, %2, %3;" : "=l"(d) : "l"(a), "l"(b), "l"(c))

__device__ __forceinline__ unsigned long long pack_f32x2(float lo, float hi) {
    unsigned long long r;
    unsigned ulo = __float_as_uint(lo), uhi = __float_as_uint(hi);
    asm("mov.b64 %0, {%1, %2};" : "=l"(r) : "r"(ulo), "r"(uhi));
    return r;
}
__device__ __forceinline__ void unpack_f32x2(unsigned long long v, float& lo, float& hi) {
    unsigned ulo, uhi;
    asm("mov.b64 {%0, %1}, %2;" : "=r"(ulo), "=r"(uhi) : "l"(v));
    lo = __uint_as_float(ulo);
    hi = __uint_as_float(uhi);
}

__device__ __forceinline__ float warp_sum(float v) {
#pragma unroll
    for (int o = 16; o > 0; o >>= 1) v += __shfl_xor_sync(0xffffffffu, v, o);
    return v;
}
__device__ __forceinline__ int warp_sum_i(int v) {
#pragma unroll
    for (int o = 16; o > 0; o >>= 1) v += __shfl_xor_sync(0xffffffffu, v, o);
    return v;
}
__device__ __forceinline__ float lrelu(float v) { return v > 0.f ? v : 0.2f * v; }

// ---------------- detect edge dtype + init degrees (fused) ------------------
__global__ void init_kernel(const unsigned* __restrict__ w, int n) {
    int i = blockIdx.x * blockDim.x + threadIdx.x;
    if (i < n) g_deg[i] = 1;  // self loop
    if (blockIdx.x == 0 && threadIdx.x == 0) {
        int all0 = 1;
        for (int k = 1; k < 64; k += 2) all0 &= (w[k] == 0u);
        g_is64 = all0;
    }
}

__global__ void convert_count_kernel(const void* __restrict__ ei, int E) {
    int i = blockIdx.x * blockDim.x + threadIdx.x;
    if (i >= E) return;
    int s, d;
    if (g_is64) {
        const long long* p = (const long long*)ei;
        s = (int)p[i];
        d = (int)p[E + i];
    } else {
        const int* p = (const int*)ei;
        s = p[i];
        d = p[E + i];
    }
    g_srcv[i] = s;
    g_dstv[i] = d;
    atomicAdd(&g_deg[d], 1);
}

// ---------------- scan: per-block sums, then block scan w/ inline prefix ----
__global__ void scan1_kernel() {
    int i = blockIdx.x * 256 + threadIdx.x;
    int v = (i < NN) ? g_deg[i] : 0;
    v = warp_sum_i(v);
    __shared__ int sw[8];
    if ((threadIdx.x & 31) == 0) sw[threadIdx.x >> 5] = v;
    __syncthreads();
    if (threadIdx.x == 0) {
        int t = 0;
#pragma unroll
        for (int k = 0; k < 8; k++) t += sw[k];
        g_bsum[blockIdx.x] = t;
    }
}

// each block computes its own exclusive prefix of g_bsum (one warp, ~7 loads)
__global__ void scan3_kernel(int E) {
    __shared__ int sh[256];
    __shared__ int base;
    int tid = threadIdx.x;
    if (tid < 32) {
        int t = 0;
        for (int j = tid; j < (int)blockIdx.x; j += 32) t += g_bsum[j];
        t = warp_sum_i(t);
        if (tid == 0) base = t;
    }
    int i = blockIdx.x * 256 + tid;
    int v = (i < NN) ? g_deg[i] : 0;
    sh[tid] = v;
    __syncthreads();
    for (int off = 1; off < 256; off <<= 1) {
        int t = (tid >= off) ? sh[tid - off] : 0;
        __syncthreads();
        sh[tid] += t;
        __syncthreads();
    }
    if (i < NN) {
        int o = base + sh[tid] - v;
        g_roff[i] = o;
        g_cur[i]  = o;
        if (i == NN - 1) g_roff[NN] = o + v;  // == NN + E
    }
}

__global__ void scatter_kernel(int E, int n) {
    int i = blockIdx.x * blockDim.x + threadIdx.x;
    int total = n + E;
    if (i >= total) return;
    int src, dst;
    if (i < n) { src = i; dst = i; }
    else       { int e = i - n; src = g_srcv[e]; dst = g_dstv[e]; }
    int p = atomicAdd(&g_cur[dst], 1);
    g_csrp[p] = (long long)(unsigned)src | ((long long)dst << 32);
}

// ---------------- per-edge softmax weights (layers 1-2) ---------------------
__global__ void weights_kernel(int total) {
    int i = blockIdx.x * blockDim.x + threadIdx.x;
    if (i >= total) return;
    long long v = g_csrp[i];
    int s = (int)v;
    int d = (int)(v >> 32);
    g_w[i] = __expf(fminf(lrelu(g_as[s] + g_ad[d]), 80.f));
}

// ---------------- GEMMs with fused score epilogue ---------------------------
// Layer 1: [N,13] @ [13,128] -> g_h16 (+ scores g_as/g_ad)
__global__ void gemm13_kernel(const float* __restrict__ x, const float* __restrict__ W,
                              const float* __restrict__ a_s, const float* __restrict__ a_d) {
    __shared__ float Ws[IND * HID];
    __shared__ float xs[16 * IND];
    __shared__ __align__(16) float hs[16 * HID];
    int tid = threadIdx.x;
    for (int j = tid; j < IND * HID; j += 128) Ws[j] = W[j];
    int base = blockIdx.x * 16;
    for (int j = tid; j < 16 * IND; j += 128) {
        int r = j / IND, k = j % IND;
        xs[j] = x[(base + r) * IND + k];
    }
    __syncthreads();
#pragma unroll 4
    for (int r = 0; r < 16; r++) {
        float acc = 0.f;
#pragma unroll
        for (int k = 0; k < IND; k++) acc += xs[r * IND + k] * Ws[k * HID + tid];
        g_h16[(base + r) * HID + tid] = __float2half(acc);
        hs[r * HID + tid] = acc;
    }
    __syncthreads();
    int wid = tid >> 5, lane = tid & 31;
    float4 s4 = ((const float4*)a_s)[lane];
    float4 d4 = ((const float4*)a_d)[lane];
#pragma unroll
    for (int i = 0; i < 4; i++) {
        int r = wid * 4 + i;
        float4 hv = ((const float4*)(hs + r * HID))[lane];
        float ps = hv.x * s4.x + hv.y * s4.y + hv.z * s4.z + hv.w * s4.w;
        float pd = hv.x * d4.x + hv.y * d4.y + hv.z * d4.z + hv.w * d4.w;
        ps = warp_sum(ps);
        pd = warp_sum(pd);
        if (lane == 0) { g_as[base + r] = ps; g_ad[base + r] = pd; }
    }
}

// Layer 2: g_hB [N,128] @ W2 [128,128] -> g_h16 (+ scores).
#define GROWS 32
__global__ void __launch_bounds__(128) gemm128_kernel(const float* __restrict__ W,
                                                      const float* __restrict__ a_s,
                                                      const float* __restrict__ a_d) {
    __shared__ __align__(16) float hs[GROWS * HID];  // 16KB, reused for epilogue
    int tid = threadIdx.x;
    int base = blockIdx.x * GROWS;
    const float4* hin4 = (const float4*)g_hB;
    float4* hs4 = (float4*)hs;
    for (int j = tid; j < GROWS * 32; j += 128) {
        int r = j >> 5, q = j & 31;
        int row = base + r;
        hs4[j] = (row < NN) ? hin4[row * 32 + q] : make_float4(0.f, 0.f, 0.f, 0.f);
    }
    __syncthreads();

    unsigned long long acc[GROWS];
#pragma unroll
    for (int r = 0; r < GROWS; r++) acc[r] = 0ull;

    for (int kq = 0; kq < 32; kq++) {
        int k0 = 4 * kq;
        float w0 = __ldg(&W[(k0 + 0) * HID + tid]);
        float w1 = __ldg(&W[(k0 + 1) * HID + tid]);
        float w2 = __ldg(&W[(k0 + 2) * HID + tid]);
        float w3 = __ldg(&W[(k0 + 3) * HID + tid]);
        unsigned long long b01 = pack_f32x2(w0, w1);
        unsigned long long b23 = pack_f32x2(w2, w3);
#pragma unroll
        for (int r = 0; r < GROWS; r++) {
            const ulonglong2 a = *(const ulonglong2*)&hs[r * HID + k0];
            FMA_F32X2(acc[r], a.x, b01, acc[r]);
            FMA_F32X2(acc[r], a.y, b23, acc[r]);
        }
    }
    __syncthreads();
#pragma unroll
    for (int r = 0; r < GROWS; r++) {
        float lo, hi;
        unpack_f32x2(acc[r], lo, hi);
        float v = lo + hi;
        hs[r * HID + tid] = v;
        if (base + r < NN) g_h16[(base + r) * HID + tid] = __float2half(v);
    }
    __syncthreads();
    int wid = tid >> 5, lane = tid & 31;
    float4 s4 = ((const float4*)a_s)[lane];
    float4 d4 = ((const float4*)a_d)[lane];
#pragma unroll
    for (int i = 0; i < 8; i++) {
        int r = wid * 8 + i;
        float4 hv = ((const float4*)(hs + r * HID))[lane];
        float ps = hv.x * s4.x + hv.y * s4.y + hv.z * s4.z + hv.w * s4.w;
        float pd = hv.x * d4.x + hv.y * d4.y + hv.z * d4.z + hv.w * d4.w;
        ps = warp_sum(ps);
        pd = warp_sum(pd);
        if (lane == 0 && base + r < NN) { g_as[base + r] = ps; g_ad[base + r] = pd; }
    }
}

// ---------------- 128-dim aggregation: half-warp per edge -------------------
// 16 lanes x uint4 (16B) cover one 256B fp16 row -> warp gathers 2 edges per
// LDG.128. Weights precomputed (g_w). alpha = w/sum(w). -> g_hB
__global__ void agg128_kernel(const float* __restrict__ bias) {
    int warp = (blockIdx.x * blockDim.x + threadIdx.x) >> 5;
    int lane = threadIdx.x & 31;
    if (warp >= NN) return;
    int e0 = g_roff[warp], e1 = g_roff[warp + 1];
    int half = lane >> 4;
    int l16  = lane & 15;

    float acc[8];
#pragma unroll
    for (int j = 0; j < 8; j++) acc[j] = 0.f;
    float s = 0.f;

    int e = e0;
    for (; e + 7 < e1; e += 8) {
#pragma unroll
        for (int p = 0; p < 4; p++) {
            int idx = e + 2 * p + half;
            int src = *(const int*)(g_csrp + idx);   // low word = src
            float w = g_w[idx];
            const uint4 u = ((const uint4*)(g_h16 + src * HID))[l16];
            s += w;
            float2 f0 = __half22float2(*(const __half2*)&u.x);
            float2 f1 = __half22float2(*(const __half2*)&u.y);
            float2 f2 = __half22float2(*(const __half2*)&u.z);
            float2 f3 = __half22float2(*(const __half2*)&u.w);
            acc[0] += w * f0.x; acc[1] += w * f0.y;
            acc[2] += w * f1.x; acc[3] += w * f1.y;
            acc[4] += w * f2.x; acc[5] += w * f2.y;
            acc[6] += w * f3.x; acc[7] += w * f3.y;
        }
    }
    for (; e + 1 < e1; e += 2) {  // pair-granular tail keeps both halves busy
        int idx = e + half;
        int src = *(const int*)(g_csrp + idx);
        float w = g_w[idx];
        const uint4 u = ((const uint4*)(g_h16 + src * HID))[l16];
        s += w;
        float2 f0 = __half22float2(*(const __half2*)&u.x);
        float2 f1 = __half22float2(*(const __half2*)&u.y);
        float2 f2 = __half22float2(*(const __half2*)&u.z);
        float2 f3 = __half22float2(*(const __half2*)&u.w);
        acc[0] += w * f0.x; acc[1] += w * f0.y;
        acc[2] += w * f1.x; acc[3] += w * f1.y;
        acc[4] += w * f2.x; acc[5] += w * f2.y;
        acc[6] += w * f3.x; acc[7] += w * f3.y;
    }
    if (e < e1) {  // at most one single edge left
        int src = *(const int*)(g_csrp + e);
        float w = (half == 0) ? g_w[e] : 0.f;
        const uint4 u = ((const uint4*)(g_h16 + src * HID))[l16];
        s += w;
        float2 f0 = __half22float2(*(const __half2*)&u.x);
        float2 f1 = __half22float2(*(const __half2*)&u.y);
        float2 f2 = __half22float2(*(const __half2*)&u.z);
        float2 f3 = __half22float2(*(const __half2*)&u.w);
        acc[0] += w * f0.x; acc[1] += w * f0.y;
        acc[2] += w * f1.x; acc[3] += w * f1.y;
        acc[4] += w * f2.x; acc[5] += w * f2.y;
        acc[6] += w * f3.x; acc[7] += w * f3.y;
    }

    s += __shfl_down_sync(0xffffffffu, s, 16);
#pragma unroll
    for (int j = 0; j < 8; j++) acc[j] += __shfl_down_sync(0xffffffffu, acc[j], 16);

    if (lane < 16) {
        float inv = 1.f / s;
        const float4* b4 = (const float4*)(bias + l16 * 8);
        float4 bA = b4[0], bB = b4[1];
        float4 oA, oB;
        oA.x = fmaxf(acc[0] * inv + bA.x, 0.f);
        oA.y = fmaxf(acc[1] * inv + bA.y, 0.f);
        oA.z = fmaxf(acc[2] * inv + bA.z, 0.f);
        oA.w = fmaxf(acc[3] * inv + bA.w, 0.f);
        oB.x = fmaxf(acc[4] * inv + bB.x, 0.f);
        oB.y = fmaxf(acc[5] * inv + bB.y, 0.f);
        oB.z = fmaxf(acc[6] * inv + bB.z, 0.f);
        oB.w = fmaxf(acc[7] * inv + bB.w, 0.f);
        float4* dst = (float4*)(g_hB + warp * HID + l16 * 8);
        dst[0] = oA;
        dst[1] = oB;
    }
}

// ---------------- layer 3 GEMM (128->5) fused with scores -------------------
__global__ void l3_kernel(const float* __restrict__ W3,
                          const float* __restrict__ a_s, const float* __restrict__ a_d) {
    __shared__ float Ws[HID * OUTD];
    int tid = threadIdx.x;
    for (int j = tid; j < HID * OUTD; j += blockDim.x) Ws[j] = W3[j];
    __syncthreads();
    int warp = (blockIdx.x * blockDim.x + tid) >> 5;
    int lane = tid & 31;
    if (warp >= NN) return;
    const float4* h4 = (const float4*)g_hB;
    float4 hv = h4[warp * 32 + lane];
    int k = 4 * lane;
    float o[OUTD];
#pragma unroll
    for (int c = 0; c < OUTD; c++) {
        float p = hv.x * Ws[(k + 0) * OUTD + c] + hv.y * Ws[(k + 1) * OUTD + c]
                + hv.z * Ws[(k + 2) * OUTD + c] + hv.w * Ws[(k + 3) * OUTD + c];
        o[c] = warp_sum(p);
    }
    if (lane == 0) {
        float as = 0.f, ad = 0.f;
#pragma unroll
        for (int c = 0; c < OUTD; c++) {
            g_h3[warp * H3S + c] = o[c];
            as += o[c] * a_s[c];
            ad += o[c] * a_d[c];
        }
        g_h3[warp * H3S + 5] = 0.f;
        g_h3[warp * H3S + 6] = 0.f;
        g_h3[warp * H3S + 7] = 0.f;
        g_as[warp] = as;
        g_ad[warp] = ad;
    }
}

// ---------------- 5-dim aggregation + log_softmax -> d_out ------------------
// weights computed inline: dst == warp so ad is one uniform load.
__global__ void agg5_kernel(const float* __restrict__ b3, float* __restrict__ out) {
    int warp = (blockIdx.x * blockDim.x + threadIdx.x) >> 5;
    int lane = threadIdx.x & 31;
    if (warp >= NN) return;
    int e = g_roff[warp], end = g_roff[warp + 1];
    float adi = g_ad[warp];

    float s = 0.f, acc = 0.f;
    for (; e + 1 < end; e += 2) {
        int s0 = *(const int*)(g_csrp + e);
        int s1 = *(const int*)(g_csrp + e + 1);
        float w0 = __expf(fminf(lrelu(g_as[s0] + adi), 80.f));
        float w1 = __expf(fminf(lrelu(g_as[s1] + adi), 80.f));
        s += w0 + w1;
        if (lane < OUTD) acc += w0 * g_h3[s0 * H3S + lane] + w1 * g_h3[s1 * H3S + lane];
    }
    if (e < end) {
        int s0 = *(const int*)(g_csrp + e);
        float w0 = __expf(fminf(lrelu(g_as[s0] + adi), 80.f));
        s += w0;
        if (lane < OUTD) acc += w0 * g_h3[s0 * H3S + lane];
    }

    float v = (lane < OUTD) ? (acc / s + b3[lane]) : -1e30f;
    float m5 = v;
#pragma unroll
    for (int o = 4; o > 0; o >>= 1) m5 = fmaxf(m5, __shfl_xor_sync(0xffffffffu, m5, o));
    float ex = (lane < OUTD) ? __expf(v - m5) : 0.f;
#pragma unroll
    for (int o = 4; o > 0; o >>= 1) ex += __shfl_xor_sync(0xffffffffu, ex, o);
    if (lane < OUTD) out[warp * OUTD + lane] = v - m5 - logf(ex);
}

// ---------------- launch ----------------------------------------------------
extern "C" void kernel_launch(void* const* d_in, const int* in_sizes, int n_in,
                              void* d_out, int out_size) {
    const float* x      = (const float*)d_in[0];
    const void*  ei     = d_in[1];
    const float* W1     = (const float*)d_in[2];
    const float* a_src1 = (const float*)d_in[3];
    const float* a_dst1 = (const float*)d_in[4];
    const float* b1     = (const float*)d_in[5];
    const float* W2     = (const float*)d_in[6];
    const float* a_src2 = (const float*)d_in[7];
    const float* a_dst2 = (const float*)d_in[8];
    const float* b2     = (const float*)d_in[9];
    const float* W3     = (const float*)d_in[10];
    const float* a_src3 = (const float*)d_in[11];
    const float* a_dst3 = (const float*)d_in[12];
    const float* b3     = (const float*)d_in[13];
    float* out = (float*)d_out;

    const int E = in_sizes[1] / 2;
    const int N = NN;
    const int total = N + E;

    // CSR build
    init_kernel<<<NB, 256>>>((const unsigned*)ei, N);
    convert_count_kernel<<<(E + 255) / 256, 256>>>(ei, E);
    scan1_kernel<<<NB, 256>>>();
    scan3_kernel<<<NB, 256>>>(E);
    scatter_kernel<<<(total + 255) / 256, 256>>>(E, N);

    // Layer 1
    gemm13_kernel<<<N / 16, 128>>>(x, W1, a_src1, a_dst1);
    weights_kernel<<<(total + 255) / 256, 256>>>(total);
    agg128_kernel<<<N / 8, 256>>>(b1);

    // Layer 2
    gemm128_kernel<<<(N + GROWS - 1) / GROWS, 128>>>(W2, a_src2, a_dst2);
    weights_kernel<<<(total + 255) / 256, 256>>>(total);
    agg128_kernel<<<N / 8, 256>>>(b2);

    // Layer 3
    l3_kernel<<<N / 8, 256>>>(W3, a_src3, a_dst3);
    agg5_kernel<<<N / 8, 256>>>(b3, out);
}

// round 15
// speedup vs baseline: 1.1038x; 1.0881x over previous
#include <cuda_runtime.h>
#include <cuda_fp16.h>

// GAT 3-layer forward on GB300.
// CSR-by-dst build (count -> merged scan -> scatter reading edge_index
// directly), per layer: dense GEMM with fused score epilogue (fp16 features
// + fp32 scores), edge-parallel weight precompute (all 3 layers),
// warp-per-node aggregation: half-warp-per-edge uint4 gathers (128-dim),
// 8-lanes-per-edge gathers (5-dim padded rows).

#define NN   50000
#define EE   1600000
#define ET   (NN + EE)     // edges + self loops
#define HID  128
#define IND  13
#define OUTD 5
#define H3S  8             // padded row stride for g_h3 (32B sectors)
#define NB   196           // ceil(NN/256)

// ---------------- scratch (device globals; no allocation allowed) ----------
__device__ __align__(16) __half g_h16[NN * HID];  // fp16 features for gathers
__device__ __align__(16) float g_hB[NN * HID];    // fp32 agg outputs / GEMM inputs
__device__ __align__(16) float g_h3[NN * H3S];    // layer-3 features, padded rows
__device__ float g_as[NN];
__device__ float g_ad[NN];
__device__ int   g_deg[NN];
__device__ int   g_roff[NN + 1];
__device__ int   g_cur[NN];
__device__ __align__(16) long long g_csrp[ET];    // packed: low=src, high=dst
__device__ __align__(16) float g_w[ET];           // per-edge softmax weight
__device__ int   g_bsum[256];
__device__ int   g_is64;

#define FMA_F32X2(d, a, b, c) \
    asm("fma.rn.f32x2 %0, %1, %2, %3;" : "=l"(d) : "l"(a), "l"(b), "l"(c))

__device__ __forceinline__ unsigned long long pack_f32x2(float lo, float hi) {
    unsigned long long r;
    unsigned ulo = __float_as_uint(lo), uhi = __float_as_uint(hi);
    asm("mov.b64 %0, {%1, %2};" : "=l"(r) : "r"(ulo), "r"(uhi));
    return r;
}
__device__ __forceinline__ void unpack_f32x2(unsigned long long v, float& lo, float& hi) {
    unsigned ulo, uhi;
    asm("mov.b64 {%0, %1}, %2;" : "=r"(ulo), "=r"(uhi) : "l"(v));
    lo = __uint_as_float(ulo);
    hi = __uint_as_float(uhi);
}

__device__ __forceinline__ float warp_sum(float v) {
#pragma unroll
    for (int o = 16; o > 0; o >>= 1) v += __shfl_xor_sync(0xffffffffu, v, o);
    return v;
}
__device__ __forceinline__ int warp_sum_i(int v) {
#pragma unroll
    for (int o = 16; o > 0; o >>= 1) v += __shfl_xor_sync(0xffffffffu, v, o);
    return v;
}
__device__ __forceinline__ float lrelu(float v) { return v > 0.f ? v : 0.2f * v; }

// ---------------- detect edge dtype + init degrees (fused) ------------------
__global__ void init_kernel(const unsigned* __restrict__ w, int n) {
    int i = blockIdx.x * blockDim.x + threadIdx.x;
    if (i < n) g_deg[i] = 1;  // self loop
    if (blockIdx.x == 0 && threadIdx.x == 0) {
        int all0 = 1;
        for (int k = 1; k < 64; k += 2) all0 &= (w[k] == 0u);
        g_is64 = all0;
    }
}

// histogram of destinations (reads only the dst half of edge_index)
__global__ void count_kernel(const void* __restrict__ ei, int E) {
    int i = blockIdx.x * blockDim.x + threadIdx.x;
    if (i >= E) return;
    int d;
    if (g_is64) d = (int)((const long long*)ei)[E + i];
    else        d = ((const int*)ei)[E + i];
    atomicAdd(&g_deg[d], 1);
}

// ---------------- scan: per-block sums, then block scan w/ inline prefix ----
__global__ void scan1_kernel() {
    int i = blockIdx.x * 256 + threadIdx.x;
    int v = (i < NN) ? g_deg[i] : 0;
    v = warp_sum_i(v);
    __shared__ int sw[8];
    if ((threadIdx.x & 31) == 0) sw[threadIdx.x >> 5] = v;
    __syncthreads();
    if (threadIdx.x == 0) {
        int t = 0;
#pragma unroll
        for (int k = 0; k < 8; k++) t += sw[k];
        g_bsum[blockIdx.x] = t;
    }
}

// each block computes its own exclusive prefix of g_bsum (one warp, ~7 loads)
__global__ void scan3_kernel(int E) {
    __shared__ int sh[256];
    __shared__ int base;
    int tid = threadIdx.x;
    if (tid < 32) {
        int t = 0;
        for (int j = tid; j < (int)blockIdx.x; j += 32) t += g_bsum[j];
        t = warp_sum_i(t);
        if (tid == 0) base = t;
    }
    int i = blockIdx.x * 256 + tid;
    int v = (i < NN) ? g_deg[i] : 0;
    sh[tid] = v;
    __syncthreads();
    for (int off = 1; off < 256; off <<= 1) {
        int t = (tid >= off) ? sh[tid - off] : 0;
        __syncthreads();
        sh[tid] += t;
        __syncthreads();
    }
    if (i < NN) {
        int o = base + sh[tid] - v;
        g_roff[i] = o;
        g_cur[i]  = o;
        if (i == NN - 1) g_roff[NN] = o + v;  // == NN + E
    }
}

// scatter reads edge_index directly (no intermediate srcv/dstv arrays)
__global__ void scatter_kernel(const void* __restrict__ ei, int E, int n) {
    int i = blockIdx.x * blockDim.x + threadIdx.x;
    int total = n + E;
    if (i >= total) return;
    int src, dst;
    if (i < n) { src = i; dst = i; }
    else {
        int e = i - n;
        if (g_is64) {
            const long long* p = (const long long*)ei;
            src = (int)p[e];
            dst = (int)p[E + e];
        } else {
            const int* p = (const int*)ei;
            src = p[e];
            dst = p[E + e];
        }
    }
    int p = atomicAdd(&g_cur[dst], 1);
    g_csrp[p] = (long long)(unsigned)src | ((long long)dst << 32);
}

// ---------------- per-edge softmax weights (all layers) ---------------------
__global__ void weights_kernel(int total) {
    int i = blockIdx.x * blockDim.x + threadIdx.x;
    if (i >= total) return;
    long long v = g_csrp[i];
    int s = (int)v;
    int d = (int)(v >> 32);
    g_w[i] = __expf(fminf(lrelu(g_as[s] + g_ad[d]), 80.f));
}

// ---------------- GEMMs with fused score epilogue ---------------------------
// Layer 1: [N,13] @ [13,128] -> g_h16 (+ scores g_as/g_ad)
__global__ void gemm13_kernel(const float* __restrict__ x, const float* __restrict__ W,
                              const float* __restrict__ a_s, const float* __restrict__ a_d) {
    __shared__ float Ws[IND * HID];
    __shared__ float xs[16 * IND];
    __shared__ __align__(16) float hs[16 * HID];
    int tid = threadIdx.x;
    for (int j = tid; j < IND * HID; j += 128) Ws[j] = W[j];
    int base = blockIdx.x * 16;
    for (int j = tid; j < 16 * IND; j += 128) {
        int r = j / IND, k = j % IND;
        xs[j] = x[(base + r) * IND + k];
    }
    __syncthreads();
#pragma unroll 4
    for (int r = 0; r < 16; r++) {
        float acc = 0.f;
#pragma unroll
        for (int k = 0; k < IND; k++) acc += xs[r * IND + k] * Ws[k * HID + tid];
        g_h16[(base + r) * HID + tid] = __float2half(acc);
        hs[r * HID + tid] = acc;
    }
    __syncthreads();
    int wid = tid >> 5, lane = tid & 31;
    float4 s4 = ((const float4*)a_s)[lane];
    float4 d4 = ((const float4*)a_d)[lane];
#pragma unroll
    for (int i = 0; i < 4; i++) {
        int r = wid * 4 + i;
        float4 hv = ((const float4*)(hs + r * HID))[lane];
        float ps = hv.x * s4.x + hv.y * s4.y + hv.z * s4.z + hv.w * s4.w;
        float pd = hv.x * d4.x + hv.y * d4.y + hv.z * d4.z + hv.w * d4.w;
        ps = warp_sum(ps);
        pd = warp_sum(pd);
        if (lane == 0) { g_as[base + r] = ps; g_ad[base + r] = pd; }
    }
}

// Layer 2: g_hB [N,128] @ W2 [128,128] -> g_h16 (+ scores).
#define GROWS 32
__global__ void __launch_bounds__(128) gemm128_kernel(const float* __restrict__ W,
                                                      const float* __restrict__ a_s,
                                                      const float* __restrict__ a_d) {
    __shared__ __align__(16) float hs[GROWS * HID];  // 16KB, reused for epilogue
    int tid = threadIdx.x;
    int base = blockIdx.x * GROWS;
    const float4* hin4 = (const float4*)g_hB;
    float4* hs4 = (float4*)hs;
    for (int j = tid; j < GROWS * 32; j += 128) {
        int r = j >> 5, q = j & 31;
        int row = base + r;
        hs4[j] = (row < NN) ? hin4[row * 32 + q] : make_float4(0.f, 0.f, 0.f, 0.f);
    }
    __syncthreads();

    unsigned long long acc[GROWS];
#pragma unroll
    for (int r = 0; r < GROWS; r++) acc[r] = 0ull;

    for (int kq = 0; kq < 32; kq++) {
        int k0 = 4 * kq;
        float w0 = __ldg(&W[(k0 + 0) * HID + tid]);
        float w1 = __ldg(&W[(k0 + 1) * HID + tid]);
        float w2 = __ldg(&W[(k0 + 2) * HID + tid]);
        float w3 = __ldg(&W[(k0 + 3) * HID + tid]);
        unsigned long long b01 = pack_f32x2(w0, w1);
        unsigned long long b23 = pack_f32x2(w2, w3);
#pragma unroll
        for (int r = 0; r < GROWS; r++) {
            const ulonglong2 a = *(const ulonglong2*)&hs[r * HID + k0];
            FMA_F32X2(acc[r], a.x, b01, acc[r]);
            FMA_F32X2(acc[r], a.y, b23, acc[r]);
        }
    }
    __syncthreads();
#pragma unroll
    for (int r = 0; r < GROWS; r++) {
        float lo, hi;
        unpack_f32x2(acc[r], lo, hi);
        float v = lo + hi;
        hs[r * HID + tid] = v;
        if (base + r < NN) g_h16[(base + r) * HID + tid] = __float2half(v);
    }
    __syncthreads();
    int wid = tid >> 5, lane = tid & 31;
    float4 s4 = ((const float4*)a_s)[lane];
    float4 d4 = ((const float4*)a_d)[lane];
#pragma unroll
    for (int i = 0; i < 8; i++) {
        int r = wid * 8 + i;
        float4 hv = ((const float4*)(hs + r * HID))[lane];
        float ps = hv.x * s4.x + hv.y * s4.y + hv.z * s4.z + hv.w * s4.w;
        float pd = hv.x * d4.x + hv.y * d4.y + hv.z * d4.z + hv.w * d4.w;
        ps = warp_sum(ps);
        pd = warp_sum(pd);
        if (lane == 0 && base + r < NN) { g_as[base + r] = ps; g_ad[base + r] = pd; }
    }
}

// ---------------- 128-dim aggregation: half-warp per edge -------------------
__global__ void agg128_kernel(const float* __restrict__ bias) {
    int warp = (blockIdx.x * blockDim.x + threadIdx.x) >> 5;
    int lane = threadIdx.x & 31;
    if (warp >= NN) return;
    int e0 = g_roff[warp], e1 = g_roff[warp + 1];
    int half = lane >> 4;
    int l16  = lane & 15;

    float acc[8];
#pragma unroll
    for (int j = 0; j < 8; j++) acc[j] = 0.f;
    float s = 0.f;

    int e = e0;
    for (; e + 7 < e1; e += 8) {
#pragma unroll
        for (int p = 0; p < 4; p++) {
            int idx = e + 2 * p + half;
            int src = *(const int*)(g_csrp + idx);   // low word = src
            float w = g_w[idx];
            const uint4 u = ((const uint4*)(g_h16 + src * HID))[l16];
            s += w;
            float2 f0 = __half22float2(*(const __half2*)&u.x);
            float2 f1 = __half22float2(*(const __half2*)&u.y);
            float2 f2 = __half22float2(*(const __half2*)&u.z);
            float2 f3 = __half22float2(*(const __half2*)&u.w);
            acc[0] += w * f0.x; acc[1] += w * f0.y;
            acc[2] += w * f1.x; acc[3] += w * f1.y;
            acc[4] += w * f2.x; acc[5] += w * f2.y;
            acc[6] += w * f3.x; acc[7] += w * f3.y;
        }
    }
    for (; e + 1 < e1; e += 2) {  // pair-granular tail keeps both halves busy
        int idx = e + half;
        int src = *(const int*)(g_csrp + idx);
        float w = g_w[idx];
        const uint4 u = ((const uint4*)(g_h16 + src * HID))[l16];
        s += w;
        float2 f0 = __half22float2(*(const __half2*)&u.x);
        float2 f1 = __half22float2(*(const __half2*)&u.y);
        float2 f2 = __half22float2(*(const __half2*)&u.z);
        float2 f3 = __half22float2(*(const __half2*)&u.w);
        acc[0] += w * f0.x; acc[1] += w * f0.y;
        acc[2] += w * f1.x; acc[3] += w * f1.y;
        acc[4] += w * f2.x; acc[5] += w * f2.y;
        acc[6] += w * f3.x; acc[7] += w * f3.y;
    }
    if (e < e1) {  // at most one single edge left
        int src = *(const int*)(g_csrp + e);
        float w = (half == 0) ? g_w[e] : 0.f;
        const uint4 u = ((const uint4*)(g_h16 + src * HID))[l16];
        s += w;
        float2 f0 = __half22float2(*(const __half2*)&u.x);
        float2 f1 = __half22float2(*(const __half2*)&u.y);
        float2 f2 = __half22float2(*(const __half2*)&u.z);
        float2 f3 = __half22float2(*(const __half2*)&u.w);
        acc[0] += w * f0.x; acc[1] += w * f0.y;
        acc[2] += w * f1.x; acc[3] += w * f1.y;
        acc[4] += w * f2.x; acc[5] += w * f2.y;
        acc[6] += w * f3.x; acc[7] += w * f3.y;
    }

    s += __shfl_down_sync(0xffffffffu, s, 16);
#pragma unroll
    for (int j = 0; j < 8; j++) acc[j] += __shfl_down_sync(0xffffffffu, acc[j], 16);

    if (lane < 16) {
        float inv = 1.f / s;
        const float4* b4 = (const float4*)(bias + l16 * 8);
        float4 bA = b4[0], bB = b4[1];
        float4 oA, oB;
        oA.x = fmaxf(acc[0] * inv + bA.x, 0.f);
        oA.y = fmaxf(acc[1] * inv + bA.y, 0.f);
        oA.z = fmaxf(acc[2] * inv + bA.z, 0.f);
        oA.w = fmaxf(acc[3] * inv + bA.w, 0.f);
        oB.x = fmaxf(acc[4] * inv + bB.x, 0.f);
        oB.y = fmaxf(acc[5] * inv + bB.y, 0.f);
        oB.z = fmaxf(acc[6] * inv + bB.z, 0.f);
        oB.w = fmaxf(acc[7] * inv + bB.w, 0.f);
        float4* dst = (float4*)(g_hB + warp * HID + l16 * 8);
        dst[0] = oA;
        dst[1] = oB;
    }
}

// ---------------- layer 3 GEMM (128->5) fused with scores -------------------
__global__ void l3_kernel(const float* __restrict__ W3,
                          const float* __restrict__ a_s, const float* __restrict__ a_d) {
    __shared__ float Ws[HID * OUTD];
    int tid = threadIdx.x;
    for (int j = tid; j < HID * OUTD; j += blockDim.x) Ws[j] = W3[j];
    __syncthreads();
    int warp = (blockIdx.x * blockDim.x + tid) >> 5;
    int lane = tid & 31;
    if (warp >= NN) return;
    const float4* h4 = (const float4*)g_hB;
    float4 hv = h4[warp * 32 + lane];
    int k = 4 * lane;
    float o[OUTD];
#pragma unroll
    for (int c = 0; c < OUTD; c++) {
        float p = hv.x * Ws[(k + 0) * OUTD + c] + hv.y * Ws[(k + 1) * OUTD + c]
                + hv.z * Ws[(k + 2) * OUTD + c] + hv.w * Ws[(k + 3) * OUTD + c];
        o[c] = warp_sum(p);
    }
    if (lane == 0) {
        float as = 0.f, ad = 0.f;
#pragma unroll
        for (int c = 0; c < OUTD; c++) {
            g_h3[warp * H3S + c] = o[c];
            as += o[c] * a_s[c];
            ad += o[c] * a_d[c];
        }
        g_h3[warp * H3S + 5] = 0.f;
        g_h3[warp * H3S + 6] = 0.f;
        g_h3[warp * H3S + 7] = 0.f;
        g_as[warp] = as;
        g_ad[warp] = ad;
    }
}

// ---------------- 5-dim aggregation + log_softmax -> d_out ------------------
// 8 lanes per edge (padded 32B rows): 4 edges per warp iteration.
__global__ void agg5_kernel(const float* __restrict__ b3, float* __restrict__ out) {
    int warp = (blockIdx.x * blockDim.x + threadIdx.x) >> 5;
    int lane = threadIdx.x & 31;
    if (warp >= NN) return;
    int e0 = g_roff[warp], e1 = g_roff[warp + 1];
    int sub = lane >> 3;   // which of 4 edges
    int col = lane & 7;    // column in padded row

    float s = 0.f, acc = 0.f;
    int e = e0;
    for (; e + 3 < e1; e += 4) {
        int idx = e + sub;
        int src = *(const int*)(g_csrp + idx);
        float w = g_w[idx];
        float f = g_h3[src * H3S + col];
        s += w;
        acc += w * f;
    }
    if (e < e1) {  // tail: up to 3 edges
        int idx = e + sub;
        bool valid = idx < e1;
        int safe = valid ? idx : e0;
        int src = *(const int*)(g_csrp + safe);
        float w = valid ? g_w[safe] : 0.f;
        float f = g_h3[src * H3S + col];
        s += w;
        acc += w * f;
    }

    // fold the 4 sub-groups; lanes 0..7 end with full sums
    s   += __shfl_down_sync(0xffffffffu, s, 16);
    acc += __shfl_down_sync(0xffffffffu, acc, 16);
    s   += __shfl_down_sync(0xffffffffu, s, 8);
    acc += __shfl_down_sync(0xffffffffu, acc, 8);

    float v = (lane < OUTD) ? (acc / s + b3[col]) : -1e30f;
    // log_softmax over cols 0..4 (all within lanes 0..7)
    float m5 = v;
#pragma unroll
    for (int o = 4; o > 0; o >>= 1) m5 = fmaxf(m5, __shfl_xor_sync(0xffffffffu, m5, o));
    float ex = (lane < OUTD) ? __expf(v - m5) : 0.f;
#pragma unroll
    for (int o = 4; o > 0; o >>= 1) ex += __shfl_xor_sync(0xffffffffu, ex, o);
    if (lane < OUTD) out[warp * OUTD + lane] = v - m5 - logf(ex);
}

// ---------------- launch ----------------------------------------------------
extern "C" void kernel_launch(void* const* d_in, const int* in_sizes, int n_in,
                              void* d_out, int out_size) {
    const float* x      = (const float*)d_in[0];
    const void*  ei     = d_in[1];
    const float* W1     = (const float*)d_in[2];
    const float* a_src1 = (const float*)d_in[3];
    const float* a_dst1 = (const float*)d_in[4];
    const float* b1     = (const float*)d_in[5];
    const float* W2     = (const float*)d_in[6];
    const float* a_src2 = (const float*)d_in[7];
    const float* a_dst2 = (const float*)d_in[8];
    const float* b2     = (const float*)d_in[9];
    const float* W3     = (const float*)d_in[10];
    const float* a_src3 = (const float*)d_in[11];
    const float* a_dst3 = (const float*)d_in[12];
    const float* b3     = (const float*)d_in[13];
    float* out = (float*)d_out;

    const int E = in_sizes[1] / 2;
    const int N = NN;
    const int total = N + E;

    // CSR build
    init_kernel<<<NB, 256>>>((const unsigned*)ei, N);
    count_kernel<<<(E + 255) / 256, 256>>>(ei, E);
    scan1_kernel<<<NB, 256>>>();
    scan3_kernel<<<NB, 256>>>(E);
    scatter_kernel<<<(total + 255) / 256, 256>>>(ei, E, N);

    // Layer 1
    gemm13_kernel<<<N / 16, 128>>>(x, W1, a_src1, a_dst1);
    weights_kernel<<<(total + 255) / 256, 256>>>(total);
    agg128_kernel<<<N / 8, 256>>>(b1);

    // Layer 2
    gemm128_kernel<<<(N + GROWS - 1) / GROWS, 128>>>(W2, a_src2, a_dst2);
    weights_kernel<<<(total + 255) / 256, 256>>>(total);
    agg128_kernel<<<N / 8, 256>>>(b2);

    // Layer 3
    l3_kernel<<<N / 8, 256>>>(W3, a_src3, a_dst3);
    weights_kernel<<<(total + 255) / 256, 256>>>(total);
    agg5_kernel<<<N / 8, 256>>>(b3, out);
}